// round 1
// baseline (speedup 1.0000x reference)
#include <cuda_runtime.h>
#include <math.h>

#define B_ 32
#define N_ 1024

// -------- scratch (no runtime allocation allowed) --------
__device__ float g_L  [(size_t)B_*N_*N_];     // 134 MB  adjacency -> Laplacian
__device__ float g_XT [(size_t)B_*512*N_];    // 67 MB   transposed features (max F=512)
__device__ float g_sq [B_*N_];
__device__ float g_dis[B_*N_];
__device__ float g_X1 [(size_t)B_*N_*512];    // Cheb x1
__device__ float g_X2 [(size_t)B_*N_*512];    // Cheb x2
__device__ float g_H1 [(size_t)B_*N_*128];
__device__ float g_H2 [(size_t)B_*N_*512];
__device__ float g_H3 [(size_t)B_*N_*1024];   // 134 MB
__device__ float g_pool[B_*1024];
__device__ float g_fc1 [B_*512];
__device__ float g_fc2 [B_*128];

// -------- transpose [B,N,F] -> [B,F,N] --------
__global__ void transpose_bnf(const float* __restrict__ X, float* __restrict__ XT, int F) {
    __shared__ float tile[32][33];
    int b = blockIdx.z;
    int n0 = blockIdx.x * 32, f0 = blockIdx.y * 32;
    const float* Xb = X + (size_t)b * N_ * F;
    float* XTb = XT + (size_t)b * F * N_;
    #pragma unroll
    for (int i = 0; i < 32; i += 8) {
        int nn = n0 + threadIdx.y + i, ff = f0 + threadIdx.x;
        if (nn < N_ && ff < F) tile[threadIdx.y + i][threadIdx.x] = Xb[(size_t)nn * F + ff];
    }
    __syncthreads();
    #pragma unroll
    for (int i = 0; i < 32; i += 8) {
        int ff = f0 + threadIdx.y + i, nn = n0 + threadIdx.x;
        if (ff < F && nn < N_) XTb[(size_t)ff * N_ + nn] = tile[threadIdx.x][threadIdx.y + i];
    }
}

// -------- per-row squared norms (warp per row) --------
__global__ void sqnorm(const float* __restrict__ X, float* __restrict__ sq, int F) {
    int row = blockIdx.x * 8 + threadIdx.y;            // over B*N rows
    const float* r = X + (size_t)row * F;
    float s = 0.f;
    for (int f = threadIdx.x; f < F; f += 32) { float v = r[f]; s += v * v; }
    #pragma unroll
    for (int o = 16; o; o >>= 1) s += __shfl_xor_sync(0xffffffffu, s, o);
    if (threadIdx.x == 0) sq[row] = s;
}

// -------- row degree -> d^{-1/2} (warp per row) --------
__global__ void rowdeg(const float* __restrict__ A, float* __restrict__ dis) {
    int row = blockIdx.x * 8 + threadIdx.y;            // over B*N rows
    const float* r = A + (size_t)row * N_;
    float s = 0.f;
    for (int m = threadIdx.x; m < N_; m += 32) s += r[m];
    #pragma unroll
    for (int o = 16; o; o >>= 1) s += __shfl_xor_sync(0xffffffffu, s, o);
    if (threadIdx.x == 0) dis[row] = rsqrtf(s);
}

// -------- L = I - dis_i * A * dis_j  (in place) --------
__global__ void makeL(float* __restrict__ A, const float* __restrict__ dis) {
    size_t idx = (size_t)blockIdx.x * blockDim.x + threadIdx.x;
    int j = (int)(idx & (N_ - 1));
    size_t t = idx >> 10;
    int i = (int)(t & (N_ - 1));
    int b = (int)(t >> 10);
    float v = -dis[b * N_ + i] * dis[b * N_ + j] * A[idx];
    if (i == j) v += 1.f;
    A[idx] = v;
}

// -------- generic 128x128x8 fp32 GEMM, batched via blockIdx.z --------
// MODE 0: C = A*B        MODE 1: C = exp(2*A*B - sq_i - sq_j)    MODE 2: C = 2*A*B - aux
template<int MODE>
__global__ __launch_bounds__(256) void gemm128(
    const float* __restrict__ Aall, const float* __restrict__ Ball, float* __restrict__ Call,
    int M, int N, int K, size_t sA, size_t sB, size_t sC,
    const float* __restrict__ sqall, const float* __restrict__ auxall)
{
    int b = blockIdx.z;
    const float* A  = Aall + (size_t)b * sA;
    const float* Bm = Ball + (size_t)b * sB;
    float* C = Call + (size_t)b * sC;
    const float* sqb = (MODE == 1) ? (sqall + (size_t)b * N_) : nullptr;
    const float* aux = (MODE == 2) ? (auxall + (size_t)b * sC) : nullptr;

    __shared__ float As[128][8];
    __shared__ float Bs[8][128];

    int tid = threadIdx.y * 16 + threadIdx.x;
    float acc[8][8];
    #pragma unroll
    for (int i = 0; i < 8; i++)
        #pragma unroll
        for (int j = 0; j < 8; j++) acc[i][j] = 0.f;

    int iBase = blockIdx.y * 128;
    int jBase = blockIdx.x * 128;

    for (int k0 = 0; k0 < K; k0 += 8) {
        #pragma unroll
        for (int it = 0; it < 4; it++) {
            int idx = tid + it * 256;
            int r = idx >> 3, c = idx & 7;
            int gr = iBase + r, gc = k0 + c;
            As[r][c] = (gr < M && gc < K) ? A[(size_t)gr * K + gc] : 0.f;
        }
        #pragma unroll
        for (int it = 0; it < 4; it++) {
            int idx = tid + it * 256;
            int r = idx >> 7, c = idx & 127;
            int gr = k0 + r, gc = jBase + c;
            Bs[r][c] = (gr < K && gc < N) ? Bm[(size_t)gr * N + gc] : 0.f;
        }
        __syncthreads();
        #pragma unroll
        for (int kk = 0; kk < 8; kk++) {
            float bv[8];
            *(float4*)&bv[0] = *(const float4*)&Bs[kk][threadIdx.x * 8];
            *(float4*)&bv[4] = *(const float4*)&Bs[kk][threadIdx.x * 8 + 4];
            #pragma unroll
            for (int ii = 0; ii < 8; ii++) {
                float av = As[threadIdx.y * 8 + ii][kk];
                #pragma unroll
                for (int jj = 0; jj < 8; jj++) acc[ii][jj] = fmaf(av, bv[jj], acc[ii][jj]);
            }
        }
        __syncthreads();
    }

    int i0 = iBase + threadIdx.y * 8;
    int j0 = jBase + threadIdx.x * 8;
    #pragma unroll
    for (int ii = 0; ii < 8; ii++) {
        int row = i0 + ii;
        if (row >= M) break;
        #pragma unroll
        for (int jj = 0; jj < 8; jj++) {
            int col = j0 + jj;
            if (col >= N) continue;
            float v = acc[ii][jj];
            if (MODE == 1) v = expf(2.f * v - sqb[row] - sqb[col]);
            else if (MODE == 2) v = 2.f * v - aux[(size_t)row * N + col];
            C[(size_t)row * N + col] = v;
        }
    }
}

// -------- feature GEMM: H = relu(X0*W0 + X1*W1 + X2*W2 + bias), M = B*N --------
__global__ __launch_bounds__(256) void gemm_feat(
    const float* __restrict__ A0, const float* __restrict__ A1, const float* __restrict__ A2,
    const float* __restrict__ W, const float* __restrict__ bias,
    float* __restrict__ C, int M, int N, int K)
{
    __shared__ float As[128][8];
    __shared__ float Bs[8][128];

    int tid = threadIdx.y * 16 + threadIdx.x;
    float acc[8][8];
    #pragma unroll
    for (int i = 0; i < 8; i++)
        #pragma unroll
        for (int j = 0; j < 8; j++) acc[i][j] = 0.f;

    int iBase = blockIdx.y * 128;
    int jBase = blockIdx.x * 128;

    for (int km = 0; km < 3; km++) {
        const float* A  = (km == 0) ? A0 : ((km == 1) ? A1 : A2);
        const float* Bm = W + (size_t)km * K * N;
        for (int k0 = 0; k0 < K; k0 += 8) {
            #pragma unroll
            for (int it = 0; it < 4; it++) {
                int idx = tid + it * 256;
                int r = idx >> 3, c = idx & 7;
                int gr = iBase + r, gc = k0 + c;
                As[r][c] = (gr < M && gc < K) ? A[(size_t)gr * K + gc] : 0.f;
            }
            #pragma unroll
            for (int it = 0; it < 4; it++) {
                int idx = tid + it * 256;
                int r = idx >> 7, c = idx & 127;
                int gr = k0 + r, gc = jBase + c;
                Bs[r][c] = (gr < K && gc < N) ? Bm[(size_t)gr * N + gc] : 0.f;
            }
            __syncthreads();
            #pragma unroll
            for (int kk = 0; kk < 8; kk++) {
                float bv[8];
                *(float4*)&bv[0] = *(const float4*)&Bs[kk][threadIdx.x * 8];
                *(float4*)&bv[4] = *(const float4*)&Bs[kk][threadIdx.x * 8 + 4];
                #pragma unroll
                for (int ii = 0; ii < 8; ii++) {
                    float av = As[threadIdx.y * 8 + ii][kk];
                    #pragma unroll
                    for (int jj = 0; jj < 8; jj++) acc[ii][jj] = fmaf(av, bv[jj], acc[ii][jj]);
                }
            }
            __syncthreads();
        }
    }

    int i0 = iBase + threadIdx.y * 8;
    int j0 = jBase + threadIdx.x * 8;
    #pragma unroll
    for (int ii = 0; ii < 8; ii++) {
        int row = i0 + ii;
        if (row >= M) break;
        #pragma unroll
        for (int jj = 0; jj < 8; jj++) {
            int col = j0 + jj;
            if (col >= N) continue;
            float v = fmaxf(acc[ii][jj] + bias[col], 0.f);
            C[(size_t)row * N + col] = v;
        }
    }
}

// -------- global max pool over nodes: [B,N,1024] -> [B,1024] --------
__global__ void maxpool(const float* __restrict__ H, float* __restrict__ out) {
    int f = blockIdx.x * 256 + threadIdx.x;
    int b = blockIdx.y;
    const float* base = H + (size_t)b * N_ * 1024 + f;
    float m = -1e30f;
    for (int n = 0; n < N_; n++) m = fmaxf(m, base[(size_t)n * 1024]);
    out[b * 1024 + f] = m;
}

// -------- small FC: one block per batch row --------
__global__ void fckernel(const float* __restrict__ in, const float* __restrict__ W,
                         const float* __restrict__ bias, float* __restrict__ out,
                         int K, int Nout, int dorelu) {
    __shared__ float s[1024];
    int b = blockIdx.x;
    for (int i = threadIdx.x; i < K; i += blockDim.x) s[i] = in[(size_t)b * K + i];
    __syncthreads();
    for (int j = threadIdx.x; j < Nout; j += blockDim.x) {
        float acc = bias[j];
        for (int i = 0; i < K; i++) acc = fmaf(s[i], W[(size_t)i * Nout + j], acc);
        if (dorelu) acc = fmaxf(acc, 0.f);
        out[(size_t)b * Nout + j] = acc;
    }
}

static void conv_layer(const float* P, int Fi, int Fo,
                       const float* W, const float* bias, float* H,
                       float* L, float* XT, float* sq, float* dis, float* X1, float* X2)
{
    dim3 tb(32, 8);
    dim3 blk(16, 16);
    transpose_bnf<<<dim3(32, (Fi + 31) / 32, B_), tb>>>(P, XT, Fi);
    sqnorm<<<B_ * N_ / 8, tb>>>(P, sq, Fi);
    // adjacency A = exp(2*X*XT - sq_i - sq_j)
    gemm128<1><<<dim3(8, 8, B_), blk>>>(P, XT, L, N_, N_, Fi,
                                        (size_t)N_ * Fi, (size_t)Fi * N_, (size_t)N_ * N_,
                                        sq, nullptr);
    rowdeg<<<B_ * N_ / 8, tb>>>(L, dis);
    makeL<<<(unsigned)((size_t)B_ * N_ * N_ / 256), 256>>>(L, dis);
    // x1 = L @ x0
    gemm128<0><<<dim3((Fi + 127) / 128, 8, B_), blk>>>(L, P, X1, N_, Fi, N_,
                                                       (size_t)N_ * N_, (size_t)N_ * Fi, (size_t)N_ * Fi,
                                                       nullptr, nullptr);
    // x2 = 2 L @ x1 - x0
    gemm128<2><<<dim3((Fi + 127) / 128, 8, B_), blk>>>(L, X1, X2, N_, Fi, N_,
                                                       (size_t)N_ * N_, (size_t)N_ * Fi, (size_t)N_ * Fi,
                                                       nullptr, P);
    // H = relu(x0 W0 + x1 W1 + x2 W2 + b)
    gemm_feat<<<dim3((Fo + 127) / 128, B_ * N_ / 128), blk>>>(P, X1, X2, W, bias, H, B_ * N_, Fo, Fi);
}

extern "C" void kernel_launch(void* const* d_in, const int* in_sizes, int n_in,
                              void* d_out, int out_size) {
    (void)in_sizes; (void)n_in; (void)out_size;
    const float* x     = (const float*)d_in[0];
    const float* W1    = (const float*)d_in[1];
    const float* b1    = (const float*)d_in[2];
    const float* W2    = (const float*)d_in[3];
    const float* b2    = (const float*)d_in[4];
    const float* W3    = (const float*)d_in[5];
    const float* b3    = (const float*)d_in[6];
    const float* fc1_w = (const float*)d_in[7];
    const float* fc1_b = (const float*)d_in[8];
    const float* fc2_w = (const float*)d_in[9];
    const float* fc2_b = (const float*)d_in[10];
    const float* fc3_w = (const float*)d_in[11];
    const float* fc3_b = (const float*)d_in[12];
    float* out = (float*)d_out;

    float *L, *XT, *sq, *dis, *X1, *X2, *H1, *H2, *H3, *pool, *f1, *f2;
    cudaGetSymbolAddress((void**)&L,   g_L);
    cudaGetSymbolAddress((void**)&XT,  g_XT);
    cudaGetSymbolAddress((void**)&sq,  g_sq);
    cudaGetSymbolAddress((void**)&dis, g_dis);
    cudaGetSymbolAddress((void**)&X1,  g_X1);
    cudaGetSymbolAddress((void**)&X2,  g_X2);
    cudaGetSymbolAddress((void**)&H1,  g_H1);
    cudaGetSymbolAddress((void**)&H2,  g_H2);
    cudaGetSymbolAddress((void**)&H3,  g_H3);
    cudaGetSymbolAddress((void**)&pool,g_pool);
    cudaGetSymbolAddress((void**)&f1,  g_fc1);
    cudaGetSymbolAddress((void**)&f2,  g_fc2);

    conv_layer(x,  6,   128,  W1, b1, H1, L, XT, sq, dis, X1, X2);
    conv_layer(H1, 128, 512,  W2, b2, H2, L, XT, sq, dis, X1, X2);
    conv_layer(H2, 512, 1024, W3, b3, H3, L, XT, sq, dis, X1, X2);

    maxpool<<<dim3(4, B_), 256>>>(H3, pool);
    fckernel<<<B_, 256>>>(pool, fc1_w, fc1_b, f1, 1024, 512, 1);
    fckernel<<<B_, 256>>>(f1,   fc2_w, fc2_b, f2, 512, 128, 1);
    fckernel<<<B_, 256>>>(f2,   fc3_w, fc3_b, out, 128, 40, 0);
}

// round 3
// speedup vs baseline: 2.9704x; 2.9704x over previous
#include <cuda_runtime.h>
#include <cuda_bf16.h>
#include <math.h>
#include <stdint.h>

#define B_ 32
#define N_ 1024
typedef __nv_bfloat16 bf16;

// ---------------- scratch (static device memory; no runtime alloc) ----------------
__device__ __align__(256) float g_A  [(size_t)B_*N_*N_];     // adjacency fp32
__device__ __align__(256) bf16  g_Lh [(size_t)B_*N_*N_];     // Laplacian hi
__device__ __align__(256) bf16  g_Ll [(size_t)B_*N_*N_];     // Laplacian lo
__device__ __align__(256) bf16  g_Xh [(size_t)B_*N_*512];    // layer input split
__device__ __align__(256) bf16  g_Xl [(size_t)B_*N_*512];
__device__ __align__(256) bf16  g_Th [(size_t)B_*512*N_];    // transposed operand split
__device__ __align__(256) bf16  g_Tl [(size_t)B_*512*N_];
__device__ __align__(256) float g_x1 [(size_t)B_*N_*512];
__device__ __align__(256) float g_x2 [(size_t)B_*N_*512];
__device__ __align__(256) bf16  g_x1h[(size_t)B_*N_*512];
__device__ __align__(256) bf16  g_x1l[(size_t)B_*N_*512];
__device__ __align__(256) bf16  g_x2h[(size_t)B_*N_*512];
__device__ __align__(256) bf16  g_x2l[(size_t)B_*N_*512];
__device__ __align__(256) float g_H1 [(size_t)B_*N_*128];
__device__ __align__(256) float g_H2 [(size_t)B_*N_*512];
__device__ __align__(256) float g_H3 [(size_t)B_*N_*1024];
__device__ __align__(256) bf16  g_Wh [1024*1536];
__device__ __align__(256) bf16  g_Wl [1024*1536];
__device__ float g_sq [B_*N_];
__device__ float g_dis[B_*N_];
__device__ float g_pool[B_*1024];
__device__ float g_f1 [B_*512];
__device__ float g_f2 [B_*128];

// ---------------- PTX helpers (base sm_103 ISA only: cp.async / ldmatrix / mma.sync) --------
__device__ __forceinline__ uint32_t smem_u32(const void* p) {
    uint32_t a;
    asm("{ .reg .u64 t; cvta.to.shared.u64 t, %1; cvt.u32.u64 %0, t; }" : "=r"(a) : "l"(p));
    return a;
}
__device__ __forceinline__ void cpa16(uint32_t s, const void* g, int sz) {
    asm volatile("cp.async.cg.shared.global [%0], [%1], 16, %2;" :: "r"(s), "l"(g), "r"(sz));
}
#define CP_COMMIT() asm volatile("cp.async.commit_group;")
#define CP_WAIT0()  asm volatile("cp.async.wait_group 0;")
#define CP_WAIT1()  asm volatile("cp.async.wait_group 1;")

__device__ __forceinline__ void ldm4(uint32_t* r, uint32_t a) {
    asm volatile("ldmatrix.sync.aligned.m8n8.x4.shared.b16 {%0,%1,%2,%3}, [%4];"
        : "=r"(r[0]), "=r"(r[1]), "=r"(r[2]), "=r"(r[3]) : "r"(a));
}
__device__ __forceinline__ void mma_bf16(float* d, const uint32_t* a, const uint32_t* b) {
    asm volatile("mma.sync.aligned.m16n8k16.row.col.f32.bf16.bf16.f32 "
        "{%0,%1,%2,%3},{%4,%5,%6,%7},{%8,%9},{%0,%1,%2,%3};"
        : "+f"(d[0]), "+f"(d[1]), "+f"(d[2]), "+f"(d[3])
        : "r"(a[0]), "r"(a[1]), "r"(a[2]), "r"(a[3]), "r"(b[0]), "r"(b[1]));
}

// smem tile: 128 rows x 64 bf16 cols, row pitch 144B (128B data + 16B pad -> conflict-free ldmatrix)
#define PITCH  144
#define TILEB  (128 * PITCH)     /* 18432 bytes per operand-limb tile */
#define STAGE  (4 * TILEB)       /* Ah | Al | Bh | Bl = 73728 */
#define SMEMSZ (2 * STAGE)       /* double buffered = 147456 */

// ---------------- split-bf16 HMMA GEMM ----------------
// C[M,Nv] = sum_seg A_seg[M,Kseg] * B[Nv,K]^T  (A row-major, B K-major [Nv,K])
// MODE 0: store   MODE 1: exp(2v - sq_i - sq_j)   MODE 2: 2v - aux   MODE 3: relu(v + bias)
template<int MODE>
__global__ __launch_bounds__(256) void gemm_mma(
    const bf16* A0h, const bf16* A0l, const bf16* A1h, const bf16* A1l,
    const bf16* A2h, const bf16* A2l,
    const bf16* Bh, const bf16* Bl,
    float* C, int M, int Nv, int K, int Kseg,
    long long sA, long long sB, long long sC,
    const float* sqv, const float* aux, const float* bias)
{
    extern __shared__ char sm[];
    uint32_t sb = smem_u32(sm);
    int tid = threadIdx.x, lane = tid & 31, w = tid >> 5;
    int wm = w & 1, wn = w >> 1;          // 2 x 4 warp grid, warp tile 64x32
    int b = blockIdx.z;
    int iBase = blockIdx.y * 128, jBase = blockIdx.x * 128;

    const bf16* a0h = A0h + (size_t)b * sA;
    const bf16* a0l = A0l + (size_t)b * sA;
    const bf16* a1h = A1h + (size_t)b * sA;
    const bf16* a1l = A1l + (size_t)b * sA;
    const bf16* a2h = A2h + (size_t)b * sA;
    const bf16* a2l = A2l + (size_t)b * sA;
    const bf16* bhp = Bh + (size_t)b * sB;
    const bf16* blp = Bl + (size_t)b * sB;

    float acc[4][4][4];
    #pragma unroll
    for (int i = 0; i < 4; i++)
        #pragma unroll
        for (int j = 0; j < 4; j++)
            #pragma unroll
            for (int k = 0; k < 4; k++) acc[i][j][k] = 0.f;

    int nk = (K + 63) >> 6;
    bool vec = ((K & 63) == 0) && ((Kseg & 63) == 0);

    auto load_vec = [&](int stg, int kc0) {
        uint32_t base = sb + stg * STAGE;
        #pragma unroll
        for (int jj = 0; jj < 4; jj++) {
            int c = tid + jj * 256;            // 1024 16B-chunks: 128 rows x 8
            int r = c >> 3, cc = c & 7;
            int kg = kc0 + cc * 8;
            uint32_t so = base + (uint32_t)(r * PITCH + cc * 16);
            int seg = kg / Kseg;
            const bf16* ph = (seg == 0) ? a0h : ((seg == 1) ? a1h : a2h);
            const bf16* pl = (seg == 0) ? a0l : ((seg == 1) ? a1l : a2l);
            size_t offA = (size_t)(iBase + r) * Kseg + (kg - seg * Kseg);
            cpa16(so,             ph + offA, 16);
            cpa16(so + TILEB,     pl + offA, 16);
            int gn = jBase + r;
            int ok = (gn < Nv) ? 16 : 0;
            size_t offB = (size_t)(ok ? gn : 0) * K + kg;
            cpa16(so + 2 * TILEB, bhp + offB, ok);
            cpa16(so + 3 * TILEB, blp + offB, ok);
        }
    };

    auto compute = [&](int stg) {
        uint32_t base = sb + stg * STAGE;
        #pragma unroll
        for (int ks = 0; ks < 4; ks++) {
            int kk = ks * 16;
            uint32_t ah[4][4], al[4][4];
            #pragma unroll
            for (int i = 0; i < 4; i++) {
                int row = wm * 64 + i * 16 + (lane & 15);
                uint32_t ca = base + (uint32_t)(row * PITCH + ((lane >> 4) * 8 + kk) * 2);
                ldm4(ah[i], ca);
                ldm4(al[i], ca + TILEB);
            }
            uint32_t bh[4][2], bl[4][2];
            #pragma unroll
            for (int jj = 0; jj < 2; jj++) {
                int rn = wn * 32 + jj * 16 + (lane & 7) + ((lane >> 4) & 1) * 8;
                uint32_t cb = base + 2 * TILEB +
                              (uint32_t)(rn * PITCH + (kk + ((lane >> 3) & 1) * 8) * 2);
                uint32_t t4[4];
                ldm4(t4, cb);
                bh[jj*2][0] = t4[0]; bh[jj*2][1] = t4[1];
                bh[jj*2+1][0] = t4[2]; bh[jj*2+1][1] = t4[3];
                ldm4(t4, cb + TILEB);
                bl[jj*2][0] = t4[0]; bl[jj*2][1] = t4[1];
                bl[jj*2+1][0] = t4[2]; bl[jj*2+1][1] = t4[3];
            }
            #pragma unroll
            for (int i = 0; i < 4; i++)
                #pragma unroll
                for (int j = 0; j < 4; j++) {
                    mma_bf16(acc[i][j], ah[i], bh[j]);   // hi*hi
                    mma_bf16(acc[i][j], ah[i], bl[j]);   // hi*lo
                    mma_bf16(acc[i][j], al[i], bh[j]);   // lo*hi
                }
        }
    };

    if (vec) {
        load_vec(0, 0); CP_COMMIT();
        for (int i = 0; i < nk; i++) {
            if (i + 1 < nk) { load_vec((i + 1) & 1, (i + 1) * 64); CP_COMMIT(); CP_WAIT1(); }
            else            { CP_WAIT0(); }
            __syncthreads();
            compute(i & 1);
            __syncthreads();
        }
    } else {
        // tiny-K path (layer 1 only)
        for (int c = tid; c < STAGE / 16; c += 256) *(uint4*)(sm + (size_t)c * 16) = make_uint4(0,0,0,0);
        __syncthreads();
        for (int i = 0; i < nk; i++) {
            for (int idx = tid; idx < 128 * 64; idx += 256) {
                int r = idx >> 6, kc = idx & 63;
                int kg = i * 64 + kc;
                uint32_t so = (uint32_t)(r * PITCH + kc * 2);
                if (kg < K) {
                    int seg = kg / Kseg, kkk = kg - seg * Kseg;
                    const bf16* ph = (seg == 0) ? a0h : ((seg == 1) ? a1h : a2h);
                    const bf16* pl = (seg == 0) ? a0l : ((seg == 1) ? a1l : a2l);
                    *(bf16*)(sm + so)          = ph[(size_t)(iBase + r) * Kseg + kkk];
                    *(bf16*)(sm + so + TILEB)  = pl[(size_t)(iBase + r) * Kseg + kkk];
                    int gn = jBase + r;
                    if (gn < Nv) {
                        *(bf16*)(sm + so + 2 * TILEB) = bhp[(size_t)gn * K + kg];
                        *(bf16*)(sm + so + 3 * TILEB) = blp[(size_t)gn * K + kg];
                    }
                }
            }
            __syncthreads();
            compute(0);
            __syncthreads();
            if (i + 1 < nk) {
                for (int c = tid; c < STAGE / 16; c += 256) *(uint4*)(sm + (size_t)c * 16) = make_uint4(0,0,0,0);
                __syncthreads();
            }
        }
    }

    // ---- epilogue ----
    int g = lane >> 2, t = lane & 3;
    float* Cb = C + (size_t)b * sC;
    #pragma unroll
    for (int i = 0; i < 4; i++) {
        #pragma unroll
        for (int rr = 0; rr < 2; rr++) {
            int row = iBase + wm * 64 + i * 16 + g + rr * 8;   // M is multiple of 128
            float sqi = (MODE == 1) ? sqv[b * N_ + row] : 0.f;
            #pragma unroll
            for (int j = 0; j < 4; j++) {
                int col = jBase + wn * 32 + j * 8 + 2 * t;
                #pragma unroll
                for (int cc = 0; cc < 2; cc++) {
                    int c2 = col + cc;
                    if (c2 < Nv) {
                        float v = acc[i][j][rr * 2 + cc];
                        if (MODE == 1)      v = expf(2.f * v - sqi - sqv[b * N_ + c2]);
                        else if (MODE == 2) v = 2.f * v - aux[(size_t)b * sC + (size_t)row * Nv + c2];
                        else if (MODE == 3) v = fmaxf(v + bias[c2], 0.f);
                        Cb[(size_t)row * Nv + c2] = v;
                    }
                }
            }
        }
    }
}

// ---------------- conversion / elementwise kernels ----------------
__global__ void split_fp32(const float* __restrict__ X, bf16* __restrict__ H, bf16* __restrict__ L, size_t n) {
    size_t i = ((size_t)blockIdx.x * 256 + threadIdx.x) * 4;
    if (i >= n) return;
    float4 v = *(const float4*)(X + i);
    bf16 hv[4], lv[4];
    float vv[4] = {v.x, v.y, v.z, v.w};
    #pragma unroll
    for (int k = 0; k < 4; k++) {
        bf16 h = __float2bfloat16(vv[k]);
        hv[k] = h;
        lv[k] = __float2bfloat16(vv[k] - __bfloat162float(h));
    }
    *(uint2*)(H + i) = *(uint2*)hv;
    *(uint2*)(L + i) = *(uint2*)lv;
}

__global__ void transpose_split(const float* __restrict__ X, bf16* __restrict__ Th, bf16* __restrict__ Tl, int F) {
    __shared__ float tile[32][33];
    int b = blockIdx.z;
    int n0 = blockIdx.x * 32, f0 = blockIdx.y * 32;
    const float* Xb = X + (size_t)b * N_ * F;
    #pragma unroll
    for (int i = 0; i < 32; i += 8) {
        int nn = n0 + threadIdx.y + i, ff = f0 + threadIdx.x;
        if (ff < F) tile[threadIdx.y + i][threadIdx.x] = Xb[(size_t)nn * F + ff];
    }
    __syncthreads();
    bf16* Thb = Th + (size_t)b * F * N_;
    bf16* Tlb = Tl + (size_t)b * F * N_;
    #pragma unroll
    for (int i = 0; i < 32; i += 8) {
        int ff = f0 + threadIdx.y + i, nn = n0 + threadIdx.x;
        if (ff < F) {
            float v = tile[threadIdx.x][threadIdx.y + i];
            bf16 h = __float2bfloat16(v);
            Thb[(size_t)ff * N_ + nn] = h;
            Tlb[(size_t)ff * N_ + nn] = __float2bfloat16(v - __bfloat162float(h));
        }
    }
}

__global__ void wtrans(const float* __restrict__ W, bf16* __restrict__ Th, bf16* __restrict__ Tl, int Fi, int Fo) {
    int kg = blockIdx.x * 32 + threadIdx.x;
    int o  = blockIdx.y * 8 + threadIdx.y;
    int Kt = 3 * Fi;
    if (kg < Kt && o < Fo) {
        int seg = kg / Fi, kc = kg - seg * Fi;
        float v = W[((size_t)seg * Fi + kc) * Fo + o];
        bf16 h = __float2bfloat16(v);
        Th[(size_t)o * Kt + kg] = h;
        Tl[(size_t)o * Kt + kg] = __float2bfloat16(v - __bfloat162float(h));
    }
}

__global__ void sqnorm(const float* __restrict__ X, float* __restrict__ sq, int F) {
    int row = blockIdx.x * 8 + threadIdx.y;
    const float* r = X + (size_t)row * F;
    float s = 0.f;
    for (int f = threadIdx.x; f < F; f += 32) { float v = r[f]; s += v * v; }
    #pragma unroll
    for (int o = 16; o; o >>= 1) s += __shfl_xor_sync(0xffffffffu, s, o);
    if (threadIdx.x == 0) sq[row] = s;
}

__global__ void rowdeg(const float* __restrict__ A, float* __restrict__ dis) {
    int row = blockIdx.x * 8 + threadIdx.y;
    const float* r = A + (size_t)row * N_;
    float s = 0.f;
    for (int m = threadIdx.x; m < N_; m += 32) s += r[m];
    #pragma unroll
    for (int o = 16; o; o >>= 1) s += __shfl_xor_sync(0xffffffffu, s, o);
    if (threadIdx.x == 0) dis[row] = rsqrtf(s);
}

__global__ void makeL_split(const float* __restrict__ A, const float* __restrict__ dis,
                            bf16* __restrict__ Lh, bf16* __restrict__ Ll) {
    size_t idx = ((size_t)blockIdx.x * 256 + threadIdx.x) * 4;
    int j0 = (int)(idx & (N_ - 1));
    size_t t = idx >> 10;
    int i = (int)(t & (N_ - 1));
    int b = (int)(t >> 10);
    float di = dis[b * N_ + i];
    float4 a = *(const float4*)(A + idx);
    float av[4] = {a.x, a.y, a.z, a.w};
    bf16 hv[4], lv[4];
    #pragma unroll
    for (int k = 0; k < 4; k++) {
        float v = -di * dis[b * N_ + j0 + k] * av[k];
        if (i == j0 + k) v += 1.f;
        bf16 h = __float2bfloat16(v);
        hv[k] = h;
        lv[k] = __float2bfloat16(v - __bfloat162float(h));
    }
    *(uint2*)(Lh + idx) = *(uint2*)hv;
    *(uint2*)(Ll + idx) = *(uint2*)lv;
}

__global__ void maxpool(const float* __restrict__ H, float* __restrict__ out) {
    int f = blockIdx.x * 256 + threadIdx.x;
    int b = blockIdx.y;
    const float* base = H + (size_t)b * N_ * 1024 + f;
    float m = -1e30f;
    for (int n = 0; n < N_; n++) m = fmaxf(m, base[(size_t)n * 1024]);
    out[b * 1024 + f] = m;
}

__global__ void fckernel(const float* __restrict__ in, const float* __restrict__ W,
                         const float* __restrict__ bias, float* __restrict__ out,
                         int K, int Nout, int dorelu) {
    __shared__ float s[1024];
    int b = blockIdx.x;
    for (int i = threadIdx.x; i < K; i += blockDim.x) s[i] = in[(size_t)b * K + i];
    __syncthreads();
    for (int j = threadIdx.x; j < Nout; j += blockDim.x) {
        float acc = bias[j];
        for (int i = 0; i < K; i++) acc = fmaf(s[i], W[(size_t)i * Nout + j], acc);
        if (dorelu) acc = fmaxf(acc, 0.f);
        out[(size_t)b * Nout + j] = acc;
    }
}

// ---------------- host orchestration ----------------
struct Ptrs {
    float *A, *x1, *x2, *sq, *dis;
    bf16 *Xh, *Xl, *Th, *Tl, *Lh, *Ll, *x1h, *x1l, *x2h, *x2l, *Wh, *Wl;
};

static void conv_layer(const float* P, int Fi, int Fo, const float* W, const float* bias,
                       float* H, const Ptrs& p)
{
    dim3 tb32(32, 8);
    size_t nx = (size_t)B_ * N_ * Fi;

    split_fp32<<<(unsigned)((nx + 1023) / 1024), 256>>>(P, p.Xh, p.Xl, nx);
    transpose_split<<<dim3(32, (Fi + 31) / 32, B_), tb32>>>(P, p.Th, p.Tl, Fi);
    sqnorm<<<B_ * N_ / 8, tb32>>>(P, p.sq, Fi);

    // adjacency: A = exp(2*X*X^T - sq_i - sq_j)   (B operand = X itself, K-major)
    gemm_mma<1><<<dim3(8, 8, B_), 256, SMEMSZ>>>(
        p.Xh, p.Xl, p.Xh, p.Xl, p.Xh, p.Xl, p.Xh, p.Xl, p.A,
        N_, N_, Fi, Fi, (long long)N_ * Fi, (long long)N_ * Fi, (long long)N_ * N_,
        p.sq, nullptr, nullptr);

    rowdeg<<<B_ * N_ / 8, tb32>>>(p.A, p.dis);
    makeL_split<<<(unsigned)((size_t)B_ * N_ * N_ / 1024), 256>>>(p.A, p.dis, p.Lh, p.Ll);

    // x1 = L @ x0   (B = x0^T, K-major over nodes)
    gemm_mma<0><<<dim3((Fi + 127) / 128, 8, B_), 256, SMEMSZ>>>(
        p.Lh, p.Ll, p.Lh, p.Ll, p.Lh, p.Ll, p.Th, p.Tl, p.x1,
        N_, Fi, N_, N_, (long long)N_ * N_, (long long)Fi * N_, (long long)N_ * Fi,
        nullptr, nullptr, nullptr);

    transpose_split<<<dim3(32, (Fi + 31) / 32, B_), tb32>>>(p.x1, p.Th, p.Tl, Fi);
    split_fp32<<<(unsigned)((nx + 1023) / 1024), 256>>>(p.x1, p.x1h, p.x1l, nx);

    // x2 = 2 L @ x1 - x0
    gemm_mma<2><<<dim3((Fi + 127) / 128, 8, B_), 256, SMEMSZ>>>(
        p.Lh, p.Ll, p.Lh, p.Ll, p.Lh, p.Ll, p.Th, p.Tl, p.x2,
        N_, Fi, N_, N_, (long long)N_ * N_, (long long)Fi * N_, (long long)N_ * Fi,
        nullptr, P, nullptr);

    split_fp32<<<(unsigned)((nx + 1023) / 1024), 256>>>(p.x2, p.x2h, p.x2l, nx);

    wtrans<<<dim3((3 * Fi + 31) / 32, (Fo + 7) / 8), tb32>>>(W, p.Wh, p.Wl, Fi, Fo);

    // H = relu(x0 W0 + x1 W1 + x2 W2 + b)  over M = B*N rows, K = 3*Fi
    gemm_mma<3><<<dim3((Fo + 127) / 128, B_ * N_ / 128, 1), 256, SMEMSZ>>>(
        p.Xh, p.Xl, p.x1h, p.x1l, p.x2h, p.x2l, p.Wh, p.Wl, H,
        B_ * N_, Fo, 3 * Fi, Fi, 0, 0, 0,
        nullptr, nullptr, bias);
}

extern "C" void kernel_launch(void* const* d_in, const int* in_sizes, int n_in,
                              void* d_out, int out_size) {
    (void)in_sizes; (void)n_in; (void)out_size;
    const float* x     = (const float*)d_in[0];
    const float* W1    = (const float*)d_in[1];
    const float* b1    = (const float*)d_in[2];
    const float* W2    = (const float*)d_in[3];
    const float* b2    = (const float*)d_in[4];
    const float* W3    = (const float*)d_in[5];
    const float* b3    = (const float*)d_in[6];
    const float* fc1_w = (const float*)d_in[7];
    const float* fc1_b = (const float*)d_in[8];
    const float* fc2_w = (const float*)d_in[9];
    const float* fc2_b = (const float*)d_in[10];
    const float* fc3_w = (const float*)d_in[11];
    const float* fc3_b = (const float*)d_in[12];
    float* out = (float*)d_out;

    cudaFuncSetAttribute(gemm_mma<0>, cudaFuncAttributeMaxDynamicSharedMemorySize, SMEMSZ);
    cudaFuncSetAttribute(gemm_mma<1>, cudaFuncAttributeMaxDynamicSharedMemorySize, SMEMSZ);
    cudaFuncSetAttribute(gemm_mma<2>, cudaFuncAttributeMaxDynamicSharedMemorySize, SMEMSZ);
    cudaFuncSetAttribute(gemm_mma<3>, cudaFuncAttributeMaxDynamicSharedMemorySize, SMEMSZ);

    Ptrs p;
    float *H1, *H2, *H3, *pool, *f1, *f2;
    cudaGetSymbolAddress((void**)&p.A,   g_A);
    cudaGetSymbolAddress((void**)&p.x1,  g_x1);
    cudaGetSymbolAddress((void**)&p.x2,  g_x2);
    cudaGetSymbolAddress((void**)&p.sq,  g_sq);
    cudaGetSymbolAddress((void**)&p.dis, g_dis);
    cudaGetSymbolAddress((void**)&p.Xh,  g_Xh);
    cudaGetSymbolAddress((void**)&p.Xl,  g_Xl);
    cudaGetSymbolAddress((void**)&p.Th,  g_Th);
    cudaGetSymbolAddress((void**)&p.Tl,  g_Tl);
    cudaGetSymbolAddress((void**)&p.Lh,  g_Lh);
    cudaGetSymbolAddress((void**)&p.Ll,  g_Ll);
    cudaGetSymbolAddress((void**)&p.x1h, g_x1h);
    cudaGetSymbolAddress((void**)&p.x1l, g_x1l);
    cudaGetSymbolAddress((void**)&p.x2h, g_x2h);
    cudaGetSymbolAddress((void**)&p.x2l, g_x2l);
    cudaGetSymbolAddress((void**)&p.Wh,  g_Wh);
    cudaGetSymbolAddress((void**)&p.Wl,  g_Wl);
    cudaGetSymbolAddress((void**)&H1,    g_H1);
    cudaGetSymbolAddress((void**)&H2,    g_H2);
    cudaGetSymbolAddress((void**)&H3,    g_H3);
    cudaGetSymbolAddress((void**)&pool,  g_pool);
    cudaGetSymbolAddress((void**)&f1,    g_f1);
    cudaGetSymbolAddress((void**)&f2,    g_f2);

    conv_layer(x,  6,   128,  W1, b1, H1, p);
    conv_layer(H1, 128, 512,  W2, b2, H2, p);
    conv_layer(H2, 512, 1024, W3, b3, H3, p);

    maxpool<<<dim3(4, B_), 256>>>(H3, pool);
    fckernel<<<B_, 256>>>(pool, fc1_w, fc1_b, f1, 1024, 512, 1);
    fckernel<<<B_, 256>>>(f1,   fc2_w, fc2_b, f2, 512, 128, 1);
    fckernel<<<B_, 256>>>(f2,   fc3_w, fc3_b, out, 128, 40, 0);
}

// round 4
// speedup vs baseline: 3.3234x; 1.1188x over previous
#include <cuda_runtime.h>
#include <cuda_bf16.h>
#include <math.h>
#include <stdint.h>

#define B_ 32
#define N_ 1024
typedef __nv_bfloat16 bf16;

// ---------------- scratch (static device memory; no runtime alloc) ----------------
__device__ __align__(256) float g_A  [(size_t)B_*N_*N_];     // adjacency fp32
__device__ __align__(256) bf16  g_Lh [(size_t)B_*N_*N_];     // Laplacian hi
__device__ __align__(256) bf16  g_Ll [(size_t)B_*N_*N_];     // Laplacian lo
__device__ __align__(256) bf16  g_Xh [(size_t)B_*N_*512];    // layer input split
__device__ __align__(256) bf16  g_Xl [(size_t)B_*N_*512];
__device__ __align__(256) bf16  g_Th [(size_t)B_*512*N_];    // transposed operand split
__device__ __align__(256) bf16  g_Tl [(size_t)B_*512*N_];
__device__ __align__(256) float g_x1 [(size_t)B_*N_*512];
__device__ __align__(256) float g_x2 [(size_t)B_*N_*512];
__device__ __align__(256) bf16  g_x1h[(size_t)B_*N_*512];
__device__ __align__(256) bf16  g_x1l[(size_t)B_*N_*512];
__device__ __align__(256) bf16  g_x2h[(size_t)B_*N_*512];
__device__ __align__(256) bf16  g_x2l[(size_t)B_*N_*512];
__device__ __align__(256) float g_H1 [(size_t)B_*N_*128];
__device__ __align__(256) float g_H2 [(size_t)B_*N_*512];
__device__ __align__(256) float g_H3 [(size_t)B_*N_*1024];
__device__ __align__(256) bf16  g_Wh [1024*1536];
__device__ __align__(256) bf16  g_Wl [1024*1536];
__device__ float g_sq [B_*N_];
__device__ float g_dis[B_*N_];
__device__ float g_pool[B_*1024];
__device__ float g_f1 [B_*512];
__device__ float g_f2 [B_*128];

// ---------------- PTX helpers (base sm_103 ISA only: cp.async / ldmatrix / mma.sync) --------
__device__ __forceinline__ uint32_t smem_u32(const void* p) {
    uint32_t a;
    asm("{ .reg .u64 t; cvta.to.shared.u64 t, %1; cvt.u32.u64 %0, t; }" : "=r"(a) : "l"(p));
    return a;
}
__device__ __forceinline__ void cpa16(uint32_t s, const void* g, int sz) {
    asm volatile("cp.async.cg.shared.global [%0], [%1], 16, %2;" :: "r"(s), "l"(g), "r"(sz));
}
#define CP_COMMIT() asm volatile("cp.async.commit_group;")
#define CP_WAIT0()  asm volatile("cp.async.wait_group 0;")
#define CP_WAIT1()  asm volatile("cp.async.wait_group 1;")

__device__ __forceinline__ void ldm4(uint32_t* r, uint32_t a) {
    asm volatile("ldmatrix.sync.aligned.m8n8.x4.shared.b16 {%0,%1,%2,%3}, [%4];"
        : "=r"(r[0]), "=r"(r[1]), "=r"(r[2]), "=r"(r[3]) : "r"(a));
}
__device__ __forceinline__ void mma_bf16(float* d, const uint32_t* a, const uint32_t* b) {
    asm volatile("mma.sync.aligned.m16n8k16.row.col.f32.bf16.bf16.f32 "
        "{%0,%1,%2,%3},{%4,%5,%6,%7},{%8,%9},{%0,%1,%2,%3};"
        : "+f"(d[0]), "+f"(d[1]), "+f"(d[2]), "+f"(d[3])
        : "r"(a[0]), "r"(a[1]), "r"(a[2]), "r"(a[3]), "r"(b[0]), "r"(b[1]));
}

// smem tile: 128 rows x 32 bf16 cols, pitch 80B (64B data + 16B pad; 5r mod 8 permutation
// => conflict-free ldmatrix). K-chunk 32, double-buffered => 80KB => 2 CTAs/SM.
#define PITCH  80
#define TILEB  (128 * PITCH)     /* 10240 bytes per operand-limb tile */
#define STAGE  (4 * TILEB)       /* Ah | Al | Bh | Bl = 40960 */
#define SMEMSZ (2 * STAGE)       /* double buffered = 81920 */

// ---------------- split-bf16 HMMA GEMM ----------------
// C[M,Nv] = sum_seg A_seg[M,Kseg] * B[Nv,K]^T  (A row-major, B K-major [Nv,K])
// MODE 0: store   MODE 1: exp(2v - sq_i - sq_j)   MODE 2: 2v - aux   MODE 3: relu(v + bias)
template<int MODE>
__global__ __launch_bounds__(256, 2) void gemm_mma(
    const bf16* A0h, const bf16* A0l, const bf16* A1h, const bf16* A1l,
    const bf16* A2h, const bf16* A2l,
    const bf16* Bh, const bf16* Bl,
    float* C, int M, int Nv, int K, int Kseg,
    long long sA, long long sB, long long sC,
    const float* sqv, const float* aux, const float* bias)
{
    extern __shared__ char sm[];
    uint32_t sb = smem_u32(sm);
    int tid = threadIdx.x, lane = tid & 31, w = tid >> 5;
    int wm = w & 1, wn = w >> 1;          // 2 x 4 warp grid, warp tile 64x32
    int b = blockIdx.z;
    int iBase = blockIdx.y * 128, jBase = blockIdx.x * 128;

    const bf16* a0h = A0h + (size_t)b * sA;
    const bf16* a0l = A0l + (size_t)b * sA;
    const bf16* a1h = A1h + (size_t)b * sA;
    const bf16* a1l = A1l + (size_t)b * sA;
    const bf16* a2h = A2h + (size_t)b * sA;
    const bf16* a2l = A2l + (size_t)b * sA;
    const bf16* bhp = Bh + (size_t)b * sB;
    const bf16* blp = Bl + (size_t)b * sB;

    float acc[4][4][4];
    #pragma unroll
    for (int i = 0; i < 4; i++)
        #pragma unroll
        for (int j = 0; j < 4; j++)
            #pragma unroll
            for (int k = 0; k < 4; k++) acc[i][j][k] = 0.f;

    int nk = (K + 31) >> 5;
    bool vec = ((K & 31) == 0) && ((Kseg & 31) == 0);

    auto load_vec = [&](int stg, int kc0) {
        uint32_t base = sb + stg * STAGE;
        #pragma unroll
        for (int jj = 0; jj < 2; jj++) {
            int c = tid + jj * 256;            // 512 (row, chunk) pairs: 128 rows x 4
            int r = c >> 2, cc = c & 3;
            int kg = kc0 + cc * 8;
            uint32_t so = base + (uint32_t)(r * PITCH + cc * 16);
            int seg = kg / Kseg;
            const bf16* ph = (seg == 0) ? a0h : ((seg == 1) ? a1h : a2h);
            const bf16* pl = (seg == 0) ? a0l : ((seg == 1) ? a1l : a2l);
            size_t offA = (size_t)(iBase + r) * Kseg + (kg - seg * Kseg);
            cpa16(so,             ph + offA, 16);
            cpa16(so + TILEB,     pl + offA, 16);
            int gn = jBase + r;
            int ok = (gn < Nv) ? 16 : 0;
            size_t offB = (size_t)(ok ? gn : 0) * K + kg;
            cpa16(so + 2 * TILEB, bhp + offB, ok);
            cpa16(so + 3 * TILEB, blp + offB, ok);
        }
    };

    auto compute = [&](int stg) {
        uint32_t base = sb + stg * STAGE;
        #pragma unroll
        for (int ks = 0; ks < 2; ks++) {
            int kk = ks * 16;
            uint32_t ah[4][4], al[4][4];
            #pragma unroll
            for (int i = 0; i < 4; i++) {
                int row = wm * 64 + i * 16 + (lane & 15);
                uint32_t ca = base + (uint32_t)(row * PITCH + ((lane >> 4) * 8 + kk) * 2);
                ldm4(ah[i], ca);
                ldm4(al[i], ca + TILEB);
            }
            uint32_t bh[4][2], bl[4][2];
            #pragma unroll
            for (int jj = 0; jj < 2; jj++) {
                int rn = wn * 32 + jj * 16 + (lane & 7) + ((lane >> 4) & 1) * 8;
                uint32_t cb = base + 2 * TILEB +
                              (uint32_t)(rn * PITCH + (kk + ((lane >> 3) & 1) * 8) * 2);
                uint32_t t4[4];
                ldm4(t4, cb);
                bh[jj*2][0] = t4[0]; bh[jj*2][1] = t4[1];
                bh[jj*2+1][0] = t4[2]; bh[jj*2+1][1] = t4[3];
                ldm4(t4, cb + TILEB);
                bl[jj*2][0] = t4[0]; bl[jj*2][1] = t4[1];
                bl[jj*2+1][0] = t4[2]; bl[jj*2+1][1] = t4[3];
            }
            #pragma unroll
            for (int i = 0; i < 4; i++)
                #pragma unroll
                for (int j = 0; j < 4; j++) {
                    mma_bf16(acc[i][j], ah[i], bh[j]);   // hi*hi
                    mma_bf16(acc[i][j], ah[i], bl[j]);   // hi*lo
                    mma_bf16(acc[i][j], al[i], bh[j]);   // lo*hi
                }
        }
    };

    if (vec) {
        load_vec(0, 0); CP_COMMIT();
        for (int i = 0; i < nk; i++) {
            if (i + 1 < nk) { load_vec((i + 1) & 1, (i + 1) * 32); CP_COMMIT(); CP_WAIT1(); }
            else            { CP_WAIT0(); }
            __syncthreads();
            compute(i & 1);
            __syncthreads();
        }
    } else {
        // tiny-K path (layer 1 only: K=6 or K=18)
        for (int c = tid; c < STAGE / 16; c += 256) *(uint4*)(sm + (size_t)c * 16) = make_uint4(0,0,0,0);
        __syncthreads();
        for (int i = 0; i < nk; i++) {
            for (int idx = tid; idx < 128 * 32; idx += 256) {
                int r = idx >> 5, kc = idx & 31;
                int kg = i * 32 + kc;
                uint32_t so = (uint32_t)(r * PITCH + kc * 2);
                if (kg < K) {
                    int seg = kg / Kseg, kkk = kg - seg * Kseg;
                    const bf16* ph = (seg == 0) ? a0h : ((seg == 1) ? a1h : a2h);
                    const bf16* pl = (seg == 0) ? a0l : ((seg == 1) ? a1l : a2l);
                    *(bf16*)(sm + so)          = ph[(size_t)(iBase + r) * Kseg + kkk];
                    *(bf16*)(sm + so + TILEB)  = pl[(size_t)(iBase + r) * Kseg + kkk];
                    int gn = jBase + r;
                    if (gn < Nv) {
                        *(bf16*)(sm + so + 2 * TILEB) = bhp[(size_t)gn * K + kg];
                        *(bf16*)(sm + so + 3 * TILEB) = blp[(size_t)gn * K + kg];
                    }
                }
            }
            __syncthreads();
            compute(0);
            __syncthreads();
            if (i + 1 < nk) {
                for (int c = tid; c < STAGE / 16; c += 256) *(uint4*)(sm + (size_t)c * 16) = make_uint4(0,0,0,0);
                __syncthreads();
            }
        }
    }

    // ---- epilogue ----
    int g = lane >> 2, t = lane & 3;
    float* Cb = C + (size_t)b * sC;
    #pragma unroll
    for (int i = 0; i < 4; i++) {
        #pragma unroll
        for (int rr = 0; rr < 2; rr++) {
            int row = iBase + wm * 64 + i * 16 + g + rr * 8;   // M is multiple of 128
            float sqi = (MODE == 1) ? sqv[b * N_ + row] : 0.f;
            #pragma unroll
            for (int j = 0; j < 4; j++) {
                int col = jBase + wn * 32 + j * 8 + 2 * t;
                #pragma unroll
                for (int cc = 0; cc < 2; cc++) {
                    int c2 = col + cc;
                    if (c2 < Nv) {
                        float v = acc[i][j][rr * 2 + cc];
                        if (MODE == 1)      v = expf(2.f * v - sqi - sqv[b * N_ + c2]);
                        else if (MODE == 2) v = 2.f * v - aux[(size_t)b * sC + (size_t)row * Nv + c2];
                        else if (MODE == 3) v = fmaxf(v + bias[c2], 0.f);
                        Cb[(size_t)row * Nv + c2] = v;
                    }
                }
            }
        }
    }
}

// ---------------- conversion / elementwise kernels ----------------
__global__ void split_fp32(const float* __restrict__ X, bf16* __restrict__ H, bf16* __restrict__ L, size_t n) {
    size_t i = ((size_t)blockIdx.x * 256 + threadIdx.x) * 4;
    if (i >= n) return;
    float4 v = *(const float4*)(X + i);
    bf16 hv[4], lv[4];
    float vv[4] = {v.x, v.y, v.z, v.w};
    #pragma unroll
    for (int k = 0; k < 4; k++) {
        bf16 h = __float2bfloat16(vv[k]);
        hv[k] = h;
        lv[k] = __float2bfloat16(vv[k] - __bfloat162float(h));
    }
    *(uint2*)(H + i) = *(uint2*)hv;
    *(uint2*)(L + i) = *(uint2*)lv;
}

__global__ void transpose_split(const float* __restrict__ X, bf16* __restrict__ Th, bf16* __restrict__ Tl, int F) {
    __shared__ float tile[32][33];
    int b = blockIdx.z;
    int n0 = blockIdx.x * 32, f0 = blockIdx.y * 32;
    const float* Xb = X + (size_t)b * N_ * F;
    #pragma unroll
    for (int i = 0; i < 32; i += 8) {
        int nn = n0 + threadIdx.y + i, ff = f0 + threadIdx.x;
        if (ff < F) tile[threadIdx.y + i][threadIdx.x] = Xb[(size_t)nn * F + ff];
    }
    __syncthreads();
    bf16* Thb = Th + (size_t)b * F * N_;
    bf16* Tlb = Tl + (size_t)b * F * N_;
    #pragma unroll
    for (int i = 0; i < 32; i += 8) {
        int ff = f0 + threadIdx.y + i, nn = n0 + threadIdx.x;
        if (ff < F) {
            float v = tile[threadIdx.x][threadIdx.y + i];
            bf16 h = __float2bfloat16(v);
            Thb[(size_t)ff * N_ + nn] = h;
            Tlb[(size_t)ff * N_ + nn] = __float2bfloat16(v - __bfloat162float(h));
        }
    }
}

__global__ void wtrans(const float* __restrict__ W, bf16* __restrict__ Th, bf16* __restrict__ Tl, int Fi, int Fo) {
    int kg = blockIdx.x * 32 + threadIdx.x;
    int o  = blockIdx.y * 8 + threadIdx.y;
    int Kt = 3 * Fi;
    if (kg < Kt && o < Fo) {
        int seg = kg / Fi, kc = kg - seg * Fi;
        float v = W[((size_t)seg * Fi + kc) * Fo + o];
        bf16 h = __float2bfloat16(v);
        Th[(size_t)o * Kt + kg] = h;
        Tl[(size_t)o * Kt + kg] = __float2bfloat16(v - __bfloat162float(h));
    }
}

__global__ void sqnorm(const float* __restrict__ X, float* __restrict__ sq, int F) {
    int row = blockIdx.x * 8 + threadIdx.y;
    const float* r = X + (size_t)row * F;
    float s = 0.f;
    for (int f = threadIdx.x; f < F; f += 32) { float v = r[f]; s += v * v; }
    #pragma unroll
    for (int o = 16; o; o >>= 1) s += __shfl_xor_sync(0xffffffffu, s, o);
    if (threadIdx.x == 0) sq[row] = s;
}

__global__ void rowdeg(const float* __restrict__ A, float* __restrict__ dis) {
    int row = blockIdx.x * 8 + threadIdx.y;
    const float* r = A + (size_t)row * N_;
    float s = 0.f;
    for (int m = threadIdx.x; m < N_; m += 32) s += r[m];
    #pragma unroll
    for (int o = 16; o; o >>= 1) s += __shfl_xor_sync(0xffffffffu, s, o);
    if (threadIdx.x == 0) dis[row] = rsqrtf(s);
}

__global__ void makeL_split(const float* __restrict__ A, const float* __restrict__ dis,
                            bf16* __restrict__ Lh, bf16* __restrict__ Ll) {
    size_t idx = ((size_t)blockIdx.x * 256 + threadIdx.x) * 4;
    int j0 = (int)(idx & (N_ - 1));
    size_t t = idx >> 10;
    int i = (int)(t & (N_ - 1));
    int b = (int)(t >> 10);
    float di = dis[b * N_ + i];
    float4 a = *(const float4*)(A + idx);
    float av[4] = {a.x, a.y, a.z, a.w};
    bf16 hv[4], lv[4];
    #pragma unroll
    for (int k = 0; k < 4; k++) {
        float v = -di * dis[b * N_ + j0 + k] * av[k];
        if (i == j0 + k) v += 1.f;
        bf16 h = __float2bfloat16(v);
        hv[k] = h;
        lv[k] = __float2bfloat16(v - __bfloat162float(h));
    }
    *(uint2*)(Lh + idx) = *(uint2*)hv;
    *(uint2*)(Ll + idx) = *(uint2*)lv;
}

__global__ void maxpool(const float* __restrict__ H, float* __restrict__ out) {
    int f = blockIdx.x * 256 + threadIdx.x;
    int b = blockIdx.y;
    const float* base = H + (size_t)b * N_ * 1024 + f;
    float m = -1e30f;
    for (int n = 0; n < N_; n++) m = fmaxf(m, base[(size_t)n * 1024]);
    out[b * 1024 + f] = m;
}

__global__ void fckernel(const float* __restrict__ in, const float* __restrict__ W,
                         const float* __restrict__ bias, float* __restrict__ out,
                         int K, int Nout, int dorelu) {
    __shared__ float s[1024];
    int b = blockIdx.x;
    for (int i = threadIdx.x; i < K; i += blockDim.x) s[i] = in[(size_t)b * K + i];
    __syncthreads();
    for (int j = threadIdx.x; j < Nout; j += blockDim.x) {
        float acc = bias[j];
        for (int i = 0; i < K; i++) acc = fmaf(s[i], W[(size_t)i * Nout + j], acc);
        if (dorelu) acc = fmaxf(acc, 0.f);
        out[(size_t)b * Nout + j] = acc;
    }
}

// ---------------- host orchestration ----------------
struct Ptrs {
    float *A, *x1, *x2, *sq, *dis;
    bf16 *Xh, *Xl, *Th, *Tl, *Lh, *Ll, *x1h, *x1l, *x2h, *x2l, *Wh, *Wl;
};

static void conv_layer(const float* P, int Fi, int Fo, const float* W, const float* bias,
                       float* H, const Ptrs& p)
{
    dim3 tb32(32, 8);
    size_t nx = (size_t)B_ * N_ * Fi;

    split_fp32<<<(unsigned)((nx + 1023) / 1024), 256>>>(P, p.Xh, p.Xl, nx);
    transpose_split<<<dim3(32, (Fi + 31) / 32, B_), tb32>>>(P, p.Th, p.Tl, Fi);
    sqnorm<<<B_ * N_ / 8, tb32>>>(P, p.sq, Fi);

    // adjacency: A = exp(2*X*X^T - sq_i - sq_j)   (B operand = X itself, K-major)
    gemm_mma<1><<<dim3(8, 8, B_), 256, SMEMSZ>>>(
        p.Xh, p.Xl, p.Xh, p.Xl, p.Xh, p.Xl, p.Xh, p.Xl, p.A,
        N_, N_, Fi, Fi, (long long)N_ * Fi, (long long)N_ * Fi, (long long)N_ * N_,
        p.sq, nullptr, nullptr);

    rowdeg<<<B_ * N_ / 8, tb32>>>(p.A, p.dis);
    makeL_split<<<(unsigned)((size_t)B_ * N_ * N_ / 1024), 256>>>(p.A, p.dis, p.Lh, p.Ll);

    // x1 = L @ x0   (B = x0^T, K-major over nodes)
    gemm_mma<0><<<dim3((Fi + 127) / 128, 8, B_), 256, SMEMSZ>>>(
        p.Lh, p.Ll, p.Lh, p.Ll, p.Lh, p.Ll, p.Th, p.Tl, p.x1,
        N_, Fi, N_, N_, (long long)N_ * N_, (long long)Fi * N_, (long long)N_ * Fi,
        nullptr, nullptr, nullptr);

    transpose_split<<<dim3(32, (Fi + 31) / 32, B_), tb32>>>(p.x1, p.Th, p.Tl, Fi);
    split_fp32<<<(unsigned)((nx + 1023) / 1024), 256>>>(p.x1, p.x1h, p.x1l, nx);

    // x2 = 2 L @ x1 - x0
    gemm_mma<2><<<dim3((Fi + 127) / 128, 8, B_), 256, SMEMSZ>>>(
        p.Lh, p.Ll, p.Lh, p.Ll, p.Lh, p.Ll, p.Th, p.Tl, p.x2,
        N_, Fi, N_, N_, (long long)N_ * N_, (long long)Fi * N_, (long long)N_ * Fi,
        nullptr, P, nullptr);

    split_fp32<<<(unsigned)((nx + 1023) / 1024), 256>>>(p.x2, p.x2h, p.x2l, nx);

    wtrans<<<dim3((3 * Fi + 31) / 32, (Fo + 7) / 8), tb32>>>(W, p.Wh, p.Wl, Fi, Fo);

    // H = relu(x0 W0 + x1 W1 + x2 W2 + b)  over M = B*N rows, K = 3*Fi
    gemm_mma<3><<<dim3((Fo + 127) / 128, B_ * N_ / 128, 1), 256, SMEMSZ>>>(
        p.Xh, p.Xl, p.x1h, p.x1l, p.x2h, p.x2l, p.Wh, p.Wl, H,
        B_ * N_, Fo, 3 * Fi, Fi, 0, 0, 0,
        nullptr, nullptr, bias);
}

extern "C" void kernel_launch(void* const* d_in, const int* in_sizes, int n_in,
                              void* d_out, int out_size) {
    (void)in_sizes; (void)n_in; (void)out_size;
    const float* x     = (const float*)d_in[0];
    const float* W1    = (const float*)d_in[1];
    const float* b1    = (const float*)d_in[2];
    const float* W2    = (const float*)d_in[3];
    const float* b2    = (const float*)d_in[4];
    const float* W3    = (const float*)d_in[5];
    const float* b3    = (const float*)d_in[6];
    const float* fc1_w = (const float*)d_in[7];
    const float* fc1_b = (const float*)d_in[8];
    const float* fc2_w = (const float*)d_in[9];
    const float* fc2_b = (const float*)d_in[10];
    const float* fc3_w = (const float*)d_in[11];
    const float* fc3_b = (const float*)d_in[12];
    float* out = (float*)d_out;

    cudaFuncSetAttribute(gemm_mma<0>, cudaFuncAttributeMaxDynamicSharedMemorySize, SMEMSZ);
    cudaFuncSetAttribute(gemm_mma<1>, cudaFuncAttributeMaxDynamicSharedMemorySize, SMEMSZ);
    cudaFuncSetAttribute(gemm_mma<2>, cudaFuncAttributeMaxDynamicSharedMemorySize, SMEMSZ);
    cudaFuncSetAttribute(gemm_mma<3>, cudaFuncAttributeMaxDynamicSharedMemorySize, SMEMSZ);

    Ptrs p;
    float *H1, *H2, *H3, *pool, *f1, *f2;
    cudaGetSymbolAddress((void**)&p.A,   g_A);
    cudaGetSymbolAddress((void**)&p.x1,  g_x1);
    cudaGetSymbolAddress((void**)&p.x2,  g_x2);
    cudaGetSymbolAddress((void**)&p.sq,  g_sq);
    cudaGetSymbolAddress((void**)&p.dis, g_dis);
    cudaGetSymbolAddress((void**)&p.Xh,  g_Xh);
    cudaGetSymbolAddress((void**)&p.Xl,  g_Xl);
    cudaGetSymbolAddress((void**)&p.Th,  g_Th);
    cudaGetSymbolAddress((void**)&p.Tl,  g_Tl);
    cudaGetSymbolAddress((void**)&p.Lh,  g_Lh);
    cudaGetSymbolAddress((void**)&p.Ll,  g_Ll);
    cudaGetSymbolAddress((void**)&p.x1h, g_x1h);
    cudaGetSymbolAddress((void**)&p.x1l, g_x1l);
    cudaGetSymbolAddress((void**)&p.x2h, g_x2h);
    cudaGetSymbolAddress((void**)&p.x2l, g_x2l);
    cudaGetSymbolAddress((void**)&p.Wh,  g_Wh);
    cudaGetSymbolAddress((void**)&p.Wl,  g_Wl);
    cudaGetSymbolAddress((void**)&H1,    g_H1);
    cudaGetSymbolAddress((void**)&H2,    g_H2);
    cudaGetSymbolAddress((void**)&H3,    g_H3);
    cudaGetSymbolAddress((void**)&pool,  g_pool);
    cudaGetSymbolAddress((void**)&f1,    g_f1);
    cudaGetSymbolAddress((void**)&f2,    g_f2);

    conv_layer(x,  6,   128,  W1, b1, H1, p);
    conv_layer(H1, 128, 512,  W2, b2, H2, p);
    conv_layer(H2, 512, 1024, W3, b3, H3, p);

    maxpool<<<dim3(4, B_), 256>>>(H3, pool);
    fckernel<<<B_, 256>>>(pool, fc1_w, fc1_b, f1, 1024, 512, 1);
    fckernel<<<B_, 256>>>(f1,   fc2_w, fc2_b, f2, 512, 128, 1);
    fckernel<<<B_, 256>>>(f2,   fc3_w, fc3_b, out, 128, 40, 0);
}